// round 7
// baseline (speedup 1.0000x reference)
#include <cuda_runtime.h>
#include <math.h>
#include <float.h>

#define RES   512
#define HID   128
#define NSEG  (HID + 1)            // 129 outer segments
#define SLOT  130                  // fixed slots per outer segment
#define KTOT  (NSEG * SLOT)        // 16770 padded final segments (fits uint16)
#define LUTBITS 13
#define LUTSHIFT (32 - LUTBITS)    // 19
#define LUTN  (1 << LUTBITS)
#define LUTE  (LUTN + 1)           // 8193 boundary entries
#define QBLOCKS (3 * (RES - 1))    // 1533 quad-builder blocks

// ---------------- persistent device tables (rebuilt every launch) ----------
__device__ float  g_flatT[KTOT];            // non-decreasing breakpoints (padded)
__device__ float2 g_flatAB[KTOT];           // (A, B+b3) per real final segment
__device__ unsigned short g_lut[LUTE];      // ordered-bin -> final segment index
__device__ float4 g_quad[3 * 512 * 512];    // 2x2 corner quads per plane (12MB)

__device__ __forceinline__ unsigned okey(float f) {
    unsigned u = __float_as_uint(f);
    return (u & 0x80000000u) ? ~u : (u | 0x80000000u);
}

// ============================================================================
// Fused setup: blocks [0,129) build the PWL tables; blocks [129,1662) build
// the quad layout (2 coalesced row loads + shfl + one float4 store each).
// ============================================================================
__global__ void setup_all(const float* __restrict__ w1,
                          const float* __restrict__ b1,
                          const float* __restrict__ w2,
                          const float* __restrict__ b2,
                          const float* __restrict__ w3,
                          const float* __restrict__ b3,
                          const float* __restrict__ xy,
                          const float* __restrict__ yz,
                          const float* __restrict__ xz) {
    int t = threadIdx.x;

    if (blockIdx.x >= NSEG) {
        // ---------------- quad builder ----------------
        int b = blockIdx.x - NSEG;
        int p = b / (RES - 1);
        int i = b % (RES - 1);
        const float* pl = (p == 0) ? xy : (p == 1) ? yz : xz;
        float a0 = pl[i * RES + t];
        float a1 = pl[(i + 1) * RES + t];
        float na0 = __shfl_down_sync(0xffffffffu, a0, 1);
        float na1 = __shfl_down_sync(0xffffffffu, a1, 1);
        if ((t & 31) == 31 && t + 1 < RES) {        // lane-31 patch-up
            na0 = pl[i * RES + t + 1];
            na1 = pl[(i + 1) * RES + t + 1];
        }
        if (t < RES - 1)
            g_quad[(p << 18) + (i << 9) + t] = make_float4(a0, na0, a1, na1);
        return;
    }

    // ---------------- PWL table setup (block = outer segment s) ----------------
    __shared__ float  sw1[HID], sb1[HID], ssort[HID], skink[HID];
    __shared__ float2 sab[HID];
    __shared__ float  spa[4][HID], spb[4][HID];
    __shared__ float  su[HID];
    __shared__ int    sval[HID], sm_m;
    int j = t & (HID - 1);
    int q = t >> 7;                 // 0..3
    int s = blockIdx.x;

    if (q == 0) {
        float w = w1[j], b = b1[j];
        sw1[j] = w; sb1[j] = b;
        su[j] = -b / w;
    }
    __syncthreads();
    if (q == 0) {
        float tj = su[j];
        int rank = 0;
        #pragma unroll 8
        for (int k = 0; k < HID; k++) {
            float tk = su[k];
            rank += (tk < tj) || (tk == tj && k < j);
        }
        ssort[rank] = tj;
    }
    __syncthreads();

    float segLo = (s == 0)   ? -FLT_MAX : ssort[s - 1];
    float segHi = (s == HID) ?  FLT_MAX : ssort[s];
    float Fm = (s == 0)   ? ssort[0] - 1.0f
             : (s == HID) ? ssort[HID - 1] + 1.0f
                          : 0.5f * (segLo + segHi);

    float pa = 0.0f, pb = 0.0f;
    #pragma unroll
    for (int ii = 0; ii < 32; ii++) {
        int i = q * 32 + ii;
        float wi = sw1[i], bi = sb1[i];
        bool act = fmaf(wi, Fm, bi) > 0.0f;
        float w2ij = __ldg(&w2[i * HID + j]);
        pa = fmaf(act ? wi : 0.0f, w2ij, pa);
        pb = fmaf(act ? bi : 0.0f, w2ij, pb);
    }
    spa[q][j] = pa; spb[q][j] = pb;
    __syncthreads();

    if (q == 0) {
        float alpha = (spa[0][j] + spa[1][j]) + (spa[2][j] + spa[3][j]);
        float beta  = (spb[0][j] + spb[1][j]) + (spb[2][j] + spb[3][j]) + b2[j];
        sab[j] = make_float2(alpha, beta);
        float u = -beta / alpha;
        bool valid = (alpha != 0.0f) && (u > segLo) && (u < segHi); // NaN->false
        su[j]   = valid ? u : FLT_MAX;
        sval[j] = valid ? 1 : 0;
    }
    __syncthreads();
    if (q == 0) {
        int m = 0, r = 0;
        float uj = su[j];
        #pragma unroll 8
        for (int k = 0; k < HID; k++) {
            m += sval[k];
            float uk = su[k];
            r += (uk < uj) || (uk == uj && k < j);
        }
        if (sval[j]) skink[r] = su[j];
        if (j == 0) sm_m = m;
    }
    __syncthreads();

    int nsub = sm_m + 1;
    int base = s * SLOT;
    float b3v = b3[0];
    int wid = t >> 5, lane = t & 31;

    for (int f = nsub + t; f < SLOT; f += 512)
        g_flatT[base + f] = segHi;

    for (int r = wid; r < nsub; r += 16) {
        float lo_r = (r == 0)        ? segLo : skink[r - 1];
        float hi_r = (r == nsub - 1) ? segHi : skink[r];
        float Fmid;
        if (lo_r == -FLT_MAX)      Fmid = hi_r - 1.0f;
        else if (hi_r == FLT_MAX)  Fmid = lo_r + 1.0f;
        else                       Fmid = 0.5f * (lo_r + hi_r);

        float A = 0.0f, B = 0.0f;
        #pragma unroll
        for (int k = lane; k < HID; k += 32) {
            float2 ab = sab[k];
            if (fmaf(ab.x, Fmid, ab.y) > 0.0f) {
                float w3k = __ldg(&w3[k]);
                A = fmaf(w3k, ab.x, A);
                B = fmaf(w3k, ab.y, B);
            }
        }
        #pragma unroll
        for (int d = 16; d; d >>= 1) {
            A += __shfl_xor_sync(0xffffffffu, A, d);
            B += __shfl_xor_sync(0xffffffffu, B, d);
        }
        int idx = base + r;
        if (lane == 0) {
            g_flatT[idx]  = lo_r;
            g_flatAB[idx] = make_float2(A, B + b3v);
        }

        bool firstAll = (s == 0)   && (r == 0);
        bool lastAll  = (s == HID) && (r == nsub - 1);
        unsigned k_lo = firstAll ? 0u : okey(lo_r);
        int b0 = (int)((k_lo + ((1u << LUTSHIFT) - 1u)) >> LUTSHIFT);
        int bnd;
        if (lastAll) {
            bnd = LUTE;
        } else {
            unsigned k_hi = okey(hi_r);
            bnd = (int)(k_hi >> LUTSHIFT) + (((k_hi & ((1u << LUTSHIFT) - 1u)) != 0u) ? 1 : 0);
        }
        for (int bb = b0 + lane; bb < bnd; bb += 32)
            g_lut[bb] = (unsigned short)idx;
    }
}

// ============================================================================
// Main kernel: 4 points/thread, tables fully SMEM-resident.
// ============================================================================
__device__ __forceinline__ float quad_lerp(float4 q, float h, float v) {
    float bottom = fmaf(q.z - q.x, h, q.x);
    float top    = fmaf(q.w - q.y, h, q.y);
    return fmaf(top - bottom, v, bottom);
}

__device__ __forceinline__ float eval_point(
    float px, float py, float pz,
    const float* sT, const float2* sAB, const unsigned short* sLut) {

    float cx = fmaf(px, 255.5f, 255.5f);   // (p+1)*0.5*511 in [0,511)
    float cy = fmaf(py, 255.5f, 255.5f);
    float cz = fmaf(pz, 255.5f, 255.5f);
    int ix = min((int)cx, RES - 2);
    int iy = min((int)cy, RES - 2);
    int iz = min((int)cz, RES - 2);
    float hx = cx - (float)ix;
    float hy = cy - (float)iy;
    float hz = cz - (float)iz;

    float4 qxy = __ldg(&g_quad[           (ix << 9) + iy]);
    float4 qyz = __ldg(&g_quad[(1 << 18) + (iy << 9) + iz]);
    float4 qxz = __ldg(&g_quad[(2 << 18) + (ix << 9) + iz]);

    float F = quad_lerp(qxy, hx, hy)
            + quad_lerp(qxz, hx, hz)
            + quad_lerp(qyz, hy, hz);

    int b = (int)(okey(F) >> LUTSHIFT);
    int lo = (int)sLut[b];
    int hi = (int)sLut[b + 1];
    while (lo < hi) {
        int mid = (lo + hi + 1) >> 1;
        bool le = sT[mid] <= F;
        lo = le ? mid : lo;
        hi = le ? hi  : mid - 1;
    }
    float2 ab = sAB[lo];
    float r;
    asm("tanh.approx.f32 %0, %1;" : "=f"(r) : "f"(fmaf(ab.x, F, ab.y)));
    return r;
}

__global__ __launch_bounds__(1024, 1)
void neusdf_main(const float* __restrict__ points,
                 float* __restrict__ out, int N) {
    extern __shared__ float sm[];
    float*          sT   = sm;                                   // [KTOT] 67,080B
    float2*         sAB  = (float2*)(sm + KTOT);                 // [KTOT] 134,160B
    unsigned short* sLut = (unsigned short*)(sm + 3 * KTOT);     // [LUTE]

    for (int i = threadIdx.x; i < KTOT; i += 1024) {
        sT[i]  = g_flatT[i];
        sAB[i] = g_flatAB[i];
    }
    for (int i = threadIdx.x; i < LUTE; i += 1024) sLut[i] = g_lut[i];
    __syncthreads();

    const float4* pp = (const float4*)points;
    float4*       op = (float4*)out;
    int G = N >> 2;                          // 4 points per group
    int gstride = gridDim.x * blockDim.x;

    for (int g = blockIdx.x * blockDim.x + threadIdx.x; g < G; g += gstride) {
        float4 a = pp[3 * g + 0];
        float4 b = pp[3 * g + 1];
        float4 c = pp[3 * g + 2];
        float4 o;
        o.x = eval_point(a.x, a.y, a.z, sT, sAB, sLut);
        o.y = eval_point(a.w, b.x, b.y, sT, sAB, sLut);
        o.z = eval_point(b.z, b.w, c.x, sT, sAB, sLut);
        o.w = eval_point(c.y, c.z, c.w, sT, sAB, sLut);
        op[g] = o;
    }
    // tail for N % 4 (N is a multiple of 4 here; kept for generality)
    int tail = N & 3;
    if (tail && blockIdx.x == 0 && threadIdx.x < tail) {
        int i = (N & ~3) + threadIdx.x;
        out[i] = eval_point(points[3*i], points[3*i+1], points[3*i+2],
                            sT, sAB, sLut);
    }
}

// ============================================================================
extern "C" void kernel_launch(void* const* d_in, const int* in_sizes, int n_in,
                              void* d_out, int out_size) {
    const float* points = (const float*)d_in[0];
    const float* xy     = (const float*)d_in[1];
    const float* yz     = (const float*)d_in[2];
    const float* xz     = (const float*)d_in[3];
    const float* w1     = (const float*)d_in[4];
    const float* b1     = (const float*)d_in[5];
    const float* w2     = (const float*)d_in[6];
    const float* b2     = (const float*)d_in[7];
    const float* w3     = (const float*)d_in[8];
    const float* b3     = (const float*)d_in[9];
    int N = in_sizes[0] / 3;

    setup_all<<<NSEG + QBLOCKS, 512>>>(w1, b1, w2, b2, w3, b3, xy, yz, xz);

    size_t smem = sizeof(float) * KTOT + sizeof(float2) * KTOT
                + sizeof(unsigned short) * (LUTE + 1);
    cudaFuncSetAttribute(neusdf_main,
                         cudaFuncAttributeMaxDynamicSharedMemorySize,
                         (int)smem);

    int nsm = 148;
    cudaDeviceGetAttribute(&nsm, cudaDevAttrMultiProcessorCount, 0);

    neusdf_main<<<nsm, 1024, smem>>>(points, (float*)d_out, N);
}

// round 8
// speedup vs baseline: 1.4332x; 1.4332x over previous
#include <cuda_runtime.h>
#include <math.h>
#include <float.h>

#define RES   512
#define HID   128
#define NSEG  (HID + 1)            // 129 outer segments
#define SLOT  130                  // fixed slots per outer segment
#define KTOT  (NSEG * SLOT)        // 16770 padded final segments (fits uint16)
#define LUTBITS 13
#define LUTSHIFT (32 - LUTBITS)    // 19
#define LUTN  (1 << LUTBITS)
#define LUTE  (LUTN + 1)           // 8193 boundary entries
#define QBLOCKS (3 * (RES - 1))    // 1533 quad-builder blocks

// ---------------- persistent device tables (rebuilt every launch) ----------
__device__ float  g_flatT[KTOT];            // non-decreasing breakpoints (padded)
__device__ float2 g_flatAB[KTOT];           // (A, B+b3) per real final segment
__device__ unsigned short g_lut[LUTE];      // ordered-bin -> final segment index
__device__ float4 g_quad[3 * 512 * 512];    // 2x2 corner quads per plane (12MB)

__device__ __forceinline__ unsigned okey(float f) {
    unsigned u = __float_as_uint(f);
    return (u & 0x80000000u) ? ~u : (u | 0x80000000u);
}

// ============================================================================
// Fused setup: blocks [0,129) build the PWL tables; blocks [129,1662) build
// the quad layout (2 coalesced row loads + shfl + one float4 store each).
// ============================================================================
__global__ void setup_all(const float* __restrict__ w1,
                          const float* __restrict__ b1,
                          const float* __restrict__ w2,
                          const float* __restrict__ b2,
                          const float* __restrict__ w3,
                          const float* __restrict__ b3,
                          const float* __restrict__ xy,
                          const float* __restrict__ yz,
                          const float* __restrict__ xz) {
    int t = threadIdx.x;

    if (blockIdx.x >= NSEG) {
        // ---------------- quad builder ----------------
        int b = blockIdx.x - NSEG;
        int p = b / (RES - 1);
        int i = b % (RES - 1);
        const float* pl = (p == 0) ? xy : (p == 1) ? yz : xz;
        float a0 = pl[i * RES + t];
        float a1 = pl[(i + 1) * RES + t];
        float na0 = __shfl_down_sync(0xffffffffu, a0, 1);
        float na1 = __shfl_down_sync(0xffffffffu, a1, 1);
        if ((t & 31) == 31 && t + 1 < RES) {        // lane-31 patch-up
            na0 = pl[i * RES + t + 1];
            na1 = pl[(i + 1) * RES + t + 1];
        }
        if (t < RES - 1)
            g_quad[(p << 18) + (i << 9) + t] = make_float4(a0, na0, a1, na1);
        return;
    }

    // ---------------- PWL table setup (block = outer segment s) ----------------
    __shared__ float  sw1[HID], sb1[HID], ssort[HID], skink[HID];
    __shared__ float2 sab[HID];
    __shared__ float  spa[4][HID], spb[4][HID];
    __shared__ float  su[HID];
    __shared__ int    sval[HID], sm_m;
    int j = t & (HID - 1);
    int q = t >> 7;                 // 0..3
    int s = blockIdx.x;

    if (q == 0) {
        float w = w1[j], b = b1[j];
        sw1[j] = w; sb1[j] = b;
        su[j] = -b / w;
    }
    __syncthreads();
    if (q == 0) {
        float tj = su[j];
        int rank = 0;
        #pragma unroll 8
        for (int k = 0; k < HID; k++) {
            float tk = su[k];
            rank += (tk < tj) || (tk == tj && k < j);
        }
        ssort[rank] = tj;
    }
    __syncthreads();

    float segLo = (s == 0)   ? -FLT_MAX : ssort[s - 1];
    float segHi = (s == HID) ?  FLT_MAX : ssort[s];
    float Fm = (s == 0)   ? ssort[0] - 1.0f
             : (s == HID) ? ssort[HID - 1] + 1.0f
                          : 0.5f * (segLo + segHi);

    float pa = 0.0f, pb = 0.0f;
    #pragma unroll
    for (int ii = 0; ii < 32; ii++) {
        int i = q * 32 + ii;
        float wi = sw1[i], bi = sb1[i];
        bool act = fmaf(wi, Fm, bi) > 0.0f;
        float w2ij = __ldg(&w2[i * HID + j]);
        pa = fmaf(act ? wi : 0.0f, w2ij, pa);
        pb = fmaf(act ? bi : 0.0f, w2ij, pb);
    }
    spa[q][j] = pa; spb[q][j] = pb;
    __syncthreads();

    if (q == 0) {
        float alpha = (spa[0][j] + spa[1][j]) + (spa[2][j] + spa[3][j]);
        float beta  = (spb[0][j] + spb[1][j]) + (spb[2][j] + spb[3][j]) + b2[j];
        sab[j] = make_float2(alpha, beta);
        float u = -beta / alpha;
        bool valid = (alpha != 0.0f) && (u > segLo) && (u < segHi); // NaN->false
        su[j]   = valid ? u : FLT_MAX;
        sval[j] = valid ? 1 : 0;
    }
    __syncthreads();
    if (q == 0) {
        int m = 0, r = 0;
        float uj = su[j];
        #pragma unroll 8
        for (int k = 0; k < HID; k++) {
            m += sval[k];
            float uk = su[k];
            r += (uk < uj) || (uk == uj && k < j);
        }
        if (sval[j]) skink[r] = su[j];
        if (j == 0) sm_m = m;
    }
    __syncthreads();

    int nsub = sm_m + 1;
    int base = s * SLOT;
    float b3v = b3[0];
    int wid = t >> 5, lane = t & 31;

    for (int f = nsub + t; f < SLOT; f += 512)
        g_flatT[base + f] = segHi;

    for (int r = wid; r < nsub; r += 16) {
        float lo_r = (r == 0)        ? segLo : skink[r - 1];
        float hi_r = (r == nsub - 1) ? segHi : skink[r];
        float Fmid;
        if (lo_r == -FLT_MAX)      Fmid = hi_r - 1.0f;
        else if (hi_r == FLT_MAX)  Fmid = lo_r + 1.0f;
        else                       Fmid = 0.5f * (lo_r + hi_r);

        float A = 0.0f, B = 0.0f;
        #pragma unroll
        for (int k = lane; k < HID; k += 32) {
            float2 ab = sab[k];
            if (fmaf(ab.x, Fmid, ab.y) > 0.0f) {
                float w3k = __ldg(&w3[k]);
                A = fmaf(w3k, ab.x, A);
                B = fmaf(w3k, ab.y, B);
            }
        }
        #pragma unroll
        for (int d = 16; d; d >>= 1) {
            A += __shfl_xor_sync(0xffffffffu, A, d);
            B += __shfl_xor_sync(0xffffffffu, B, d);
        }
        int idx = base + r;
        if (lane == 0) {
            g_flatT[idx]  = lo_r;
            g_flatAB[idx] = make_float2(A, B + b3v);
        }

        bool firstAll = (s == 0)   && (r == 0);
        bool lastAll  = (s == HID) && (r == nsub - 1);
        unsigned k_lo = firstAll ? 0u : okey(lo_r);
        int b0 = (int)((k_lo + ((1u << LUTSHIFT) - 1u)) >> LUTSHIFT);
        int bnd;
        if (lastAll) {
            bnd = LUTE;
        } else {
            unsigned k_hi = okey(hi_r);
            bnd = (int)(k_hi >> LUTSHIFT) + (((k_hi & ((1u << LUTSHIFT) - 1u)) != 0u) ? 1 : 0);
        }
        for (int bb = b0 + lane; bb < bnd; bb += 32)
            g_lut[bb] = (unsigned short)idx;
    }
}

// ============================================================================
// Main kernel: 2 points/thread; sT + sLut in SMEM, flatAB via L2 __ldg.
// ============================================================================
__device__ __forceinline__ float quad_lerp(float4 q, float h, float v) {
    float bottom = fmaf(q.z - q.x, h, q.x);
    float top    = fmaf(q.w - q.y, h, q.y);
    return fmaf(top - bottom, v, bottom);
}

__device__ __forceinline__ float eval_point(
    float px, float py, float pz,
    const float* sT, const unsigned short* sLut) {

    float cx = fmaf(px, 255.5f, 255.5f);   // (p+1)*0.5*511 in [0,511)
    float cy = fmaf(py, 255.5f, 255.5f);
    float cz = fmaf(pz, 255.5f, 255.5f);
    int ix = min((int)cx, RES - 2);
    int iy = min((int)cy, RES - 2);
    int iz = min((int)cz, RES - 2);
    float hx = cx - (float)ix;
    float hy = cy - (float)iy;
    float hz = cz - (float)iz;

    float4 qxy = __ldg(&g_quad[           (ix << 9) + iy]);
    float4 qyz = __ldg(&g_quad[(1 << 18) + (iy << 9) + iz]);
    float4 qxz = __ldg(&g_quad[(2 << 18) + (ix << 9) + iz]);

    float F = quad_lerp(qxy, hx, hy)
            + quad_lerp(qxz, hx, hz)
            + quad_lerp(qyz, hy, hz);

    int b = (int)(okey(F) >> LUTSHIFT);
    int lo = (int)sLut[b];
    int hi = (int)sLut[b + 1];
    while (lo < hi) {
        int mid = (lo + hi + 1) >> 1;
        bool le = sT[mid] <= F;
        lo = le ? mid : lo;
        hi = le ? hi  : mid - 1;
    }
    float2 ab = __ldg(&g_flatAB[lo]);
    float r;
    asm("tanh.approx.f32 %0, %1;" : "=f"(r) : "f"(fmaf(ab.x, F, ab.y)));
    return r;
}

__global__ __launch_bounds__(1024, 1)
void neusdf_main(const float* __restrict__ points,
                 float* __restrict__ out, int N) {
    extern __shared__ float sm[];
    float*          sT   = sm;                              // [KTOT]
    unsigned short* sLut = (unsigned short*)(sm + KTOT);    // [LUTE]

    for (int i = threadIdx.x; i < KTOT; i += 1024) sT[i] = g_flatT[i];
    for (int i = threadIdx.x; i < LUTE; i += 1024) sLut[i] = g_lut[i];
    __syncthreads();

    const float2* pp = (const float2*)points;
    float2*       op = (float2*)out;
    int G = N >> 1;
    int gstride = gridDim.x * blockDim.x;

    for (int g = blockIdx.x * blockDim.x + threadIdx.x; g < G; g += gstride) {
        float2 u = pp[3 * g + 0];
        float2 v = pp[3 * g + 1];
        float2 w = pp[3 * g + 2];
        float o0 = eval_point(u.x, u.y, v.x, sT, sLut);
        float o1 = eval_point(v.y, w.x, w.y, sT, sLut);
        op[g] = make_float2(o0, o1);
    }
    if ((N & 1) && blockIdx.x == 0 && threadIdx.x == 0) {
        int i = N - 1;
        out[i] = eval_point(points[3*i], points[3*i+1], points[3*i+2], sT, sLut);
    }
}

// ============================================================================
extern "C" void kernel_launch(void* const* d_in, const int* in_sizes, int n_in,
                              void* d_out, int out_size) {
    const float* points = (const float*)d_in[0];
    const float* xy     = (const float*)d_in[1];
    const float* yz     = (const float*)d_in[2];
    const float* xz     = (const float*)d_in[3];
    const float* w1     = (const float*)d_in[4];
    const float* b1     = (const float*)d_in[5];
    const float* w2     = (const float*)d_in[6];
    const float* b2     = (const float*)d_in[7];
    const float* w3     = (const float*)d_in[8];
    const float* b3     = (const float*)d_in[9];
    int N = in_sizes[0] / 3;

    setup_all<<<NSEG + QBLOCKS, 512>>>(w1, b1, w2, b2, w3, b3, xy, yz, xz);

    size_t smem = sizeof(float) * KTOT + sizeof(unsigned short) * (LUTE + 1);
    cudaFuncSetAttribute(neusdf_main,
                         cudaFuncAttributeMaxDynamicSharedMemorySize,
                         (int)smem);

    int nsm = 148;
    cudaDeviceGetAttribute(&nsm, cudaDevAttrMultiProcessorCount, 0);

    neusdf_main<<<nsm, 1024, smem>>>(points, (float*)d_out, N);
}

// round 9
// speedup vs baseline: 1.4876x; 1.0380x over previous
#include <cuda_runtime.h>
#include <math.h>
#include <float.h>

#define RES   512
#define HID   128
#define NSEG  (HID + 1)            // 129 outer segments
#define SLOT  130                  // fixed slots per outer segment
#define KTOT  (NSEG * SLOT)        // 16770 padded final segments (fits uint16)
#define QBLOCKS (3 * (RES - 1))    // 1533 quad-builder blocks

// ---- linear LUT over F in [LUT_LO, LUT_HI), 32768 bins + edge slack ----
#define NB      32768
#define LUT_LO  (-8.0f)
#define LUT_HI  ( 8.0f)
#define LSCALE  2048.0f            // NB / (HI - LO)
#define LUTE    (NB + 3)           // entries b = 0 .. NB+2, edge(b) = LO+(b-1)/LSCALE

// ---------------- persistent device tables (rebuilt every launch) ----------
__device__ float  g_flatT[KTOT];            // non-decreasing breakpoints (padded)
__device__ float2 g_flatAB[KTOT];           // (A, B+b3) per real final segment
__device__ unsigned short g_lut[LUTE];      // edge(b) -> max{idx: T[idx] <= edge(b)}
__device__ float4 g_quad[3 * 512 * 512];    // 2x2 corner quads per plane (12MB)

// ============================================================================
// Fused setup: blocks [0,129) build the PWL tables; blocks [129,1662) build
// the quad layout.
// ============================================================================
__global__ void setup_all(const float* __restrict__ w1,
                          const float* __restrict__ b1,
                          const float* __restrict__ w2,
                          const float* __restrict__ b2,
                          const float* __restrict__ w3,
                          const float* __restrict__ b3,
                          const float* __restrict__ xy,
                          const float* __restrict__ yz,
                          const float* __restrict__ xz) {
    int t = threadIdx.x;

    if (blockIdx.x >= NSEG) {
        // ---------------- quad builder ----------------
        int b = blockIdx.x - NSEG;
        int p = b / (RES - 1);
        int i = b % (RES - 1);
        const float* pl = (p == 0) ? xy : (p == 1) ? yz : xz;
        float a0 = pl[i * RES + t];
        float a1 = pl[(i + 1) * RES + t];
        float na0 = __shfl_down_sync(0xffffffffu, a0, 1);
        float na1 = __shfl_down_sync(0xffffffffu, a1, 1);
        if ((t & 31) == 31 && t + 1 < RES) {        // lane-31 patch-up
            na0 = pl[i * RES + t + 1];
            na1 = pl[(i + 1) * RES + t + 1];
        }
        if (t < RES - 1)
            g_quad[(p << 18) + (i << 9) + t] = make_float4(a0, na0, a1, na1);
        return;
    }

    // ---------------- PWL table setup (block = outer segment s) ----------------
    __shared__ float  sw1[HID], sb1[HID], ssort[HID], skink[HID];
    __shared__ float2 sab[HID];
    __shared__ float  spa[4][HID], spb[4][HID];
    __shared__ float  su[HID];
    __shared__ int    sval[HID], sm_m;
    int j = t & (HID - 1);
    int q = t >> 7;                 // 0..3
    int s = blockIdx.x;

    if (q == 0) {
        float w = w1[j], b = b1[j];
        sw1[j] = w; sb1[j] = b;
        su[j] = -b / w;
    }
    __syncthreads();
    if (q == 0) {
        float tj = su[j];
        int rank = 0;
        #pragma unroll 8
        for (int k = 0; k < HID; k++) {
            float tk = su[k];
            rank += (tk < tj) || (tk == tj && k < j);
        }
        ssort[rank] = tj;
    }
    __syncthreads();

    float segLo = (s == 0)   ? -FLT_MAX : ssort[s - 1];
    float segHi = (s == HID) ?  FLT_MAX : ssort[s];
    float Fm = (s == 0)   ? ssort[0] - 1.0f
             : (s == HID) ? ssort[HID - 1] + 1.0f
                          : 0.5f * (segLo + segHi);

    float pa = 0.0f, pb = 0.0f;
    #pragma unroll
    for (int ii = 0; ii < 32; ii++) {
        int i = q * 32 + ii;
        float wi = sw1[i], bi = sb1[i];
        bool act = fmaf(wi, Fm, bi) > 0.0f;
        float w2ij = __ldg(&w2[i * HID + j]);
        pa = fmaf(act ? wi : 0.0f, w2ij, pa);
        pb = fmaf(act ? bi : 0.0f, w2ij, pb);
    }
    spa[q][j] = pa; spb[q][j] = pb;
    __syncthreads();

    if (q == 0) {
        float alpha = (spa[0][j] + spa[1][j]) + (spa[2][j] + spa[3][j]);
        float beta  = (spb[0][j] + spb[1][j]) + (spb[2][j] + spb[3][j]) + b2[j];
        sab[j] = make_float2(alpha, beta);
        float u = -beta / alpha;
        bool valid = (alpha != 0.0f) && (u > segLo) && (u < segHi); // NaN->false
        su[j]   = valid ? u : FLT_MAX;
        sval[j] = valid ? 1 : 0;
    }
    __syncthreads();
    if (q == 0) {
        int m = 0, r = 0;
        float uj = su[j];
        #pragma unroll 8
        for (int k = 0; k < HID; k++) {
            m += sval[k];
            float uk = su[k];
            r += (uk < uj) || (uk == uj && k < j);
        }
        if (sval[j]) skink[r] = su[j];
        if (j == 0) sm_m = m;
    }
    __syncthreads();

    int nsub = sm_m + 1;
    int base = s * SLOT;
    float b3v = b3[0];
    int wid = t >> 5, lane = t & 31;

    for (int f = nsub + t; f < SLOT; f += 512)
        g_flatT[base + f] = segHi;

    for (int r = wid; r < nsub; r += 16) {
        float lo_r = (r == 0)        ? segLo : skink[r - 1];
        float hi_r = (r == nsub - 1) ? segHi : skink[r];
        float Fmid;
        if (lo_r == -FLT_MAX)      Fmid = hi_r - 1.0f;
        else if (hi_r == FLT_MAX)  Fmid = lo_r + 1.0f;
        else                       Fmid = 0.5f * (lo_r + hi_r);

        float A = 0.0f, B = 0.0f;
        #pragma unroll
        for (int k = lane; k < HID; k += 32) {
            float2 ab = sab[k];
            if (fmaf(ab.x, Fmid, ab.y) > 0.0f) {
                float w3k = __ldg(&w3[k]);
                A = fmaf(w3k, ab.x, A);
                B = fmaf(w3k, ab.y, B);
            }
        }
        #pragma unroll
        for (int d = 16; d; d >>= 1) {
            A += __shfl_xor_sync(0xffffffffu, A, d);
            B += __shfl_xor_sync(0xffffffffu, B, d);
        }
        int idx = base + r;
        if (lane == 0) {
            g_flatT[idx]  = lo_r;
            g_flatAB[idx] = make_float2(A, B + b3v);
        }

        // ---- LUT scatter: own bins b with lo_r <= edge(b) < hi_r,
        //      edge(b) = LUT_LO + (b-1)/LSCALE.
        //      Adjacent segments compute the shared boundary from the SAME
        //      endpoint value with identical fp ops -> exact tiling. ----
        float v0 = fmaf(lo_r - LUT_LO, LSCALE, 1.0f);
        float v1 = fmaf(hi_r - LUT_LO, LSCALE, 1.0f);
        v0 = fminf(fmaxf(v0, 0.0f), (float)LUTE);   // -inf/+inf safe
        v1 = fminf(fmaxf(v1, 0.0f), (float)LUTE);
        int b0 = (int)ceilf(v0);
        int bnd = (int)ceilf(v1);
        for (int bb = b0 + lane; bb < bnd; bb += 32)
            g_lut[bb] = (unsigned short)idx;
    }
}

// ============================================================================
// Main kernel: 2 points/thread; sT + sLut in SMEM, flatAB via L2 __ldg.
// ============================================================================
__device__ __forceinline__ float quad_lerp(float4 q, float h, float v) {
    float bottom = fmaf(q.z - q.x, h, q.x);
    float top    = fmaf(q.w - q.y, h, q.y);
    return fmaf(top - bottom, v, bottom);
}

__device__ __forceinline__ float eval_point(
    float px, float py, float pz,
    const float* sT, const unsigned short* sLut) {

    float cx = fmaf(px, 255.5f, 255.5f);   // (p+1)*0.5*511 in [0,511)
    float cy = fmaf(py, 255.5f, 255.5f);
    float cz = fmaf(pz, 255.5f, 255.5f);
    int ix = min((int)cx, RES - 2);
    int iy = min((int)cy, RES - 2);
    int iz = min((int)cz, RES - 2);
    float hx = cx - (float)ix;
    float hy = cy - (float)iy;
    float hz = cz - (float)iz;

    float4 qxy = __ldg(&g_quad[           (ix << 9) + iy]);
    float4 qyz = __ldg(&g_quad[(1 << 18) + (iy << 9) + iz]);
    float4 qxz = __ldg(&g_quad[(2 << 18) + (ix << 9) + iz]);

    float F = quad_lerp(qxy, hx, hy)
            + quad_lerp(qxz, hx, hz)
            + quad_lerp(qyz, hy, hz);

    // linear bin with +-1 bin slack (absorbs fp rounding exactly)
    float tb = fmaf(F - LUT_LO, LSCALE, 0.0f);
    int bq = min(max((int)tb, 0), NB - 1) + 1;      // 1 .. NB
    int lo = (int)sLut[bq - 1];
    int hi = (int)sLut[bq + 1];
    if (F <  LUT_LO) lo = 0;                        // ~never taken
    if (F >= LUT_HI) hi = KTOT - 1;                 // ~never taken
    while (lo < hi) {
        int mid = (lo + hi + 1) >> 1;
        bool le = sT[mid] <= F;
        lo = le ? mid : lo;
        hi = le ? hi  : mid - 1;
    }
    float2 ab = __ldg(&g_flatAB[lo]);
    float r;
    asm("tanh.approx.f32 %0, %1;" : "=f"(r) : "f"(fmaf(ab.x, F, ab.y)));
    return r;
}

__global__ __launch_bounds__(1024, 1)
void neusdf_main(const float* __restrict__ points,
                 float* __restrict__ out, int N) {
    extern __shared__ float sm[];
    float*          sT   = sm;                              // [KTOT]  67,080B
    unsigned short* sLut = (unsigned short*)(sm + KTOT);    // [LUTE]  65,542B

    for (int i = threadIdx.x; i < KTOT; i += 1024) sT[i] = g_flatT[i];
    for (int i = threadIdx.x; i < LUTE; i += 1024) sLut[i] = g_lut[i];
    __syncthreads();

    const float2* pp = (const float2*)points;
    float2*       op = (float2*)out;
    int G = N >> 1;
    int gstride = gridDim.x * blockDim.x;

    for (int g = blockIdx.x * blockDim.x + threadIdx.x; g < G; g += gstride) {
        float2 u = pp[3 * g + 0];
        float2 v = pp[3 * g + 1];
        float2 w = pp[3 * g + 2];
        float o0 = eval_point(u.x, u.y, v.x, sT, sLut);
        float o1 = eval_point(v.y, w.x, w.y, sT, sLut);
        op[g] = make_float2(o0, o1);
    }
    if ((N & 1) && blockIdx.x == 0 && threadIdx.x == 0) {
        int i = N - 1;
        out[i] = eval_point(points[3*i], points[3*i+1], points[3*i+2], sT, sLut);
    }
}

// ============================================================================
extern "C" void kernel_launch(void* const* d_in, const int* in_sizes, int n_in,
                              void* d_out, int out_size) {
    const float* points = (const float*)d_in[0];
    const float* xy     = (const float*)d_in[1];
    const float* yz     = (const float*)d_in[2];
    const float* xz     = (const float*)d_in[3];
    const float* w1     = (const float*)d_in[4];
    const float* b1     = (const float*)d_in[5];
    const float* w2     = (const float*)d_in[6];
    const float* b2     = (const float*)d_in[7];
    const float* w3     = (const float*)d_in[8];
    const float* b3     = (const float*)d_in[9];
    int N = in_sizes[0] / 3;

    setup_all<<<NSEG + QBLOCKS, 512>>>(w1, b1, w2, b2, w3, b3, xy, yz, xz);

    size_t smem = sizeof(float) * KTOT + sizeof(unsigned short) * (LUTE + 1);
    cudaFuncSetAttribute(neusdf_main,
                         cudaFuncAttributeMaxDynamicSharedMemorySize,
                         (int)smem);

    int nsm = 148;
    cudaDeviceGetAttribute(&nsm, cudaDevAttrMultiProcessorCount, 0);

    neusdf_main<<<nsm, 1024, smem>>>(points, (float*)d_out, N);
}